// round 9
// baseline (speedup 1.0000x reference)
#include <cuda_runtime.h>
#include <cuda_bf16.h>
#include <stdint.h>
#include <math.h>

// ---------------- problem constants ----------------
#define TSTEPS 128
#define BATCH  1024
#define INDIM  47
#define HID    646
#define OUTDIM 5

// ---------------- tiling ----------------
#define MTILE 128
#define NTILE 64
#define KC    32                  // k-chunk (bf16)
#define NT    11                  // 704/64
#define TILES 88                  // per job
#define NPAD  704
#define HPAD  704
#define XPAD  64
#define TPB   256
#define GRID  296

#define SST    40                 // smem row stride (bf16)
#define A_TILE (MTILE * SST)      // 5120 bf16
#define W_TILE (NTILE * SST)      // 2560 bf16
#define STAGE  (2 * A_TILE + 2 * W_TILE)   // 15360 bf16
#define NSTAGE 3
#define SMEM_BYTES (NSTAGE * STAGE * 2)    // 92160 B

// ---------------- device globals (no allocation allowed) ----------------
#define W_IH0_OFF 0
#define W_HH0_OFF (NPAD * XPAD)
#define W_IH1_OFF (W_HH0_OFF + NPAD * HPAD)
#define W_HH1_OFF (W_IH1_OFF + NPAD * HPAD)
#define W_TOT     (W_HH1_OFF + NPAD * HPAD)

__device__ __align__(16) __nv_bfloat16 gx_h[(size_t)TSTEPS * BATCH * XPAD];
__device__ __align__(16) __nv_bfloat16 gx_l[(size_t)TSTEPS * BATCH * XPAD];
__device__ __align__(16) __nv_bfloat16 gW_h[W_TOT];
__device__ __align__(16) __nv_bfloat16 gW_l[W_TOT];
__device__ __align__(16) __nv_bfloat16 gh0_h[2 * BATCH * HPAD];
__device__ __align__(16) __nv_bfloat16 gh0_l[2 * BATCH * HPAD];
__device__ __align__(16) __nv_bfloat16 gh1_h[2 * BATCH * HPAD];
__device__ __align__(16) __nv_bfloat16 gh1_l[2 * BATCH * HPAD];
__device__ unsigned int g_counter[TSTEPS + 2];

// ---------------- helpers ----------------
__device__ __forceinline__ uint32_t pkbf(float lo, float hi) {
    uint32_t r;
    asm("cvt.rn.bf16x2.f32 %0, %1, %2;" : "=r"(r) : "f"(hi), "f"(lo));
    return r;
}
__device__ __forceinline__ float fast_tanh(float x) {
    float e = __expf(2.0f * x);
    return 1.0f - __fdividef(2.0f, e + 1.0f);
}
__device__ __forceinline__ void mma_bf16(float* d, const uint32_t a[4], const uint32_t* b) {
    asm volatile(
        "mma.sync.aligned.m16n8k16.row.col.f32.bf16.bf16.f32 "
        "{%0,%1,%2,%3}, {%4,%5,%6,%7}, {%8,%9}, {%0,%1,%2,%3};"
        : "+f"(d[0]), "+f"(d[1]), "+f"(d[2]), "+f"(d[3])
        : "r"(a[0]), "r"(a[1]), "r"(a[2]), "r"(a[3]), "r"(b[0]), "r"(b[1]));
}
#define LDSM_X4(R, addr) \
    asm volatile("ldmatrix.sync.aligned.m8n8.x4.shared.b16 {%0,%1,%2,%3}, [%4];" \
        : "=r"((R)[0]), "=r"((R)[1]), "=r"((R)[2]), "=r"((R)[3]) : "r"(addr))
#define CPA16(dst, src) \
    asm volatile("cp.async.cg.shared.global [%0], [%1], 16;" :: "r"(dst), "l"(src))
#define CPA_COMMIT() asm volatile("cp.async.commit_group;" ::: "memory")
#define CPA_WAIT0()  asm volatile("cp.async.wait_group 0;" ::: "memory")
#define CPA_WAIT1()  asm volatile("cp.async.wait_group 1;" ::: "memory")

// ---------------- preprocessing ----------------
__global__ void convert_pad_kernel(__nv_bfloat16* dh, __nv_bfloat16* dl,
                                   const float* __restrict__ src,
                                   int rreal, int creal, int cpad, long total) {
    long i = (long)blockIdx.x * blockDim.x + threadIdx.x;
    if (i >= total) return;
    int r = (int)(i / cpad), c = (int)(i % cpad);
    float v = (r < rreal && c < creal) ? src[(long)r * creal + c] : 0.0f;
    __nv_bfloat16 hi = __float2bfloat16(v);
    dh[i] = hi;
    dl[i] = __float2bfloat16(v - __bfloat162float(hi));
}

__global__ void init_kernel() {
    int i = blockIdx.x * blockDim.x + threadIdx.x;
    __nv_bfloat16 z = __float2bfloat16(0.0f);
    if (i < 2 * BATCH * HPAD) {
        gh0_h[i] = z; gh0_l[i] = z; gh1_h[i] = z; gh1_l[i] = z;
    }
    if (i < TSTEPS + 2) g_counter[i] = 0u;
}

// ---------------- cell kernel ----------------
struct Seg {
    const __nv_bfloat16 *Ah, *Al;
    const __nv_bfloat16 *Wh, *Wl;
    int kpad, chunks;
};
struct Job {
    Seg s[2];
    const float *b1, *b2;
    __nv_bfloat16 *Ch, *Cl;
};

// issue cp.async for chunk c into stage buffer (6 x 16B per thread)
__device__ __forceinline__ void issue_chunk(const Job& jb, int c, int m0, int n0,
                                            int tid, uint32_t st_u32) {
    const Seg& S = (c < jb.s[0].chunks) ? jb.s[0] : jb.s[1];
    const int cc = (c < jb.s[0].chunks) ? c : c - jb.s[0].chunks;
    const int col0 = cc * KC;
    const size_t kp = S.kpad;
    const int r0 = tid >> 2,          c8a = (tid & 3) * 8;
    const int r1 = (tid + 256) >> 2,  c8b = ((tid + 256) & 3) * 8;
    const __nv_bfloat16* ah = S.Ah + (size_t)m0 * kp + col0;
    const __nv_bfloat16* al = S.Al + (size_t)m0 * kp + col0;
    CPA16(st_u32 + (r0 * SST + c8a) * 2,                ah + (size_t)r0 * kp + c8a);
    CPA16(st_u32 + (r1 * SST + c8b) * 2,                ah + (size_t)r1 * kp + c8b);
    CPA16(st_u32 + (A_TILE + r0 * SST + c8a) * 2,       al + (size_t)r0 * kp + c8a);
    CPA16(st_u32 + (A_TILE + r1 * SST + c8b) * 2,       al + (size_t)r1 * kp + c8b);
    const int nr = tid >> 2, nc = (tid & 3) * 8;
    CPA16(st_u32 + (2 * A_TILE + nr * SST + nc) * 2,
          S.Wh + (size_t)(n0 + nr) * kp + col0 + nc);
    CPA16(st_u32 + (2 * A_TILE + W_TILE + nr * SST + nc) * 2,
          S.Wl + (size_t)(n0 + nr) * kp + col0 + nc);
}

__global__ __launch_bounds__(TPB, 2) void cell_kernel(Job jH, Job jL,
                                                      int cidx, int ntiles) {
    extern __shared__ __nv_bfloat16 sm[];
    __shared__ float s_bias[NTILE];
    __shared__ unsigned int s_idx;

    const int tid = threadIdx.x, lane = tid & 31, wid = tid >> 5;
    const int wm0 = (wid & 3) * 32;
    const int wn0 = (wid >> 2) * 32;
    const int r0 = lane >> 2;
    const int c0 = (lane & 3) * 2;

    const uint32_t sm_u32 = (uint32_t)__cvta_generic_to_shared(sm);

    // ldmatrix lane addressing
    const int lt = lane >> 3, lr = lane & 7;
    uint32_t offA[2][2];
    #pragma unroll
    for (int i = 0; i < 2; i++)
        #pragma unroll
        for (int s = 0; s < 2; s++)
            offA[i][s] = ((wm0 + i * 16 + (lt & 1) * 8 + lr) * SST + s * 16 + (lt >> 1) * 8) * 2;
    uint32_t offB[2][2];
    #pragma unroll
    for (int jp = 0; jp < 2; jp++)
        #pragma unroll
        for (int s = 0; s < 2; s++)
            offB[jp][s] = ((wn0 + (2 * jp + (lt >> 1)) * 8 + lr) * SST + s * 16 + (lt & 1) * 8) * 2;

    for (;;) {
        if (tid == 0) s_idx = atomicAdd(&g_counter[cidx], 1u);
        __syncthreads();   // s_idx handoff; also: all warps done with prev tile's smem/bias
        const unsigned int idx = s_idx;
        if (idx >= (unsigned int)ntiles) break;

        const Job& jb = (idx < TILES) ? jH : jL;
        const int tile = (idx < TILES) ? (int)idx : (int)idx - TILES;
        const int m0 = (tile / NT) * MTILE;
        const int n0 = (tile % NT) * NTILE;

        if (tid < NTILE) {
            int n = n0 + tid;
            s_bias[tid] = (n < HID) ? (jb.b1[n] + jb.b2[n]) : 0.0f;
        }

        float acc[2][4][4] = {};
        const int nch = jb.s[0].chunks + jb.s[1].chunks;   // >= 24 always

        // 3-stage prologue: chunks 0,1 in flight
        issue_chunk(jb, 0, m0, n0, tid, sm_u32);
        CPA_COMMIT();
        issue_chunk(jb, 1, m0, n0, tid, sm_u32 + STAGE * 2);
        CPA_COMMIT();

        int bc = 0;          // buffer of chunk c
        int bn = 2;          // buffer of chunk c+2
        for (int c = 0; c < nch; c++) {
            // chunk c ready when <=1 group pending (c+1 still in flight)
            if (c + 1 < nch) CPA_WAIT1(); else CPA_WAIT0();
            __syncthreads();  // (a) chunk c visible to all warps
                              // (b) all warps finished compute(c-1) -> buffer bn reusable
            if (c + 2 < nch) {
                issue_chunk(jb, c + 2, m0, n0, tid, sm_u32 + bn * STAGE * 2);
                CPA_COMMIT();
            }

            const uint32_t sb = sm_u32 + bc * STAGE * 2;
            #pragma unroll
            for (int s = 0; s < 2; s++) {
                uint32_t ah[2][4], al[2][4], bh[2][4], bl[2][4];
                #pragma unroll
                for (int i = 0; i < 2; i++) {
                    LDSM_X4(ah[i], sb + offA[i][s]);
                    LDSM_X4(al[i], sb + offA[i][s] + A_TILE * 2);
                }
                #pragma unroll
                for (int jp = 0; jp < 2; jp++) {
                    LDSM_X4(bh[jp], sb + offB[jp][s] + 2 * A_TILE * 2);
                    LDSM_X4(bl[jp], sb + offB[jp][s] + (2 * A_TILE + W_TILE) * 2);
                }
                #pragma unroll
                for (int i = 0; i < 2; i++)
                    #pragma unroll
                    for (int j = 0; j < 4; j++) {
                        const uint32_t* pbh = &bh[j >> 1][(j & 1) * 2];
                        const uint32_t* pbl = &bl[j >> 1][(j & 1) * 2];
                        mma_bf16(acc[i][j], ah[i], pbh);
                        mma_bf16(acc[i][j], ah[i], pbl);
                        mma_bf16(acc[i][j], al[i], pbh);
                    }
            }
            bc = (bc == NSTAGE - 1) ? 0 : bc + 1;
            bn = (bn == NSTAGE - 1) ? 0 : bn + 1;
        }

        // epilogue: bias + tanh, store h as bf16 hi/lo pairs
        #pragma unroll
        for (int i = 0; i < 2; i++) {
            const int grow = m0 + wm0 + i * 16 + r0;
            #pragma unroll
            for (int j = 0; j < 4; j++) {
                const int col = wn0 + j * 8 + c0;
                const float bv0 = s_bias[col], bv1 = s_bias[col + 1];
                const size_t o0 = (size_t)grow * HPAD + n0 + col;
                const size_t o1 = (size_t)(grow + 8) * HPAD + n0 + col;
                float t00 = fast_tanh(acc[i][j][0] + bv0);
                float t01 = fast_tanh(acc[i][j][1] + bv1);
                float t10 = fast_tanh(acc[i][j][2] + bv0);
                float t11 = fast_tanh(acc[i][j][3] + bv1);
                uint32_t u0 = pkbf(t00, t01);
                uint32_t u1 = pkbf(t10, t11);
                *(uint32_t*)(jb.Ch + o0) = u0;
                *(uint32_t*)(jb.Ch + o1) = u1;
                float s00 = t00 - __uint_as_float(u0 << 16);
                float s01 = t01 - __uint_as_float(u0 & 0xFFFF0000u);
                float s10 = t10 - __uint_as_float(u1 << 16);
                float s11 = t11 - __uint_as_float(u1 & 0xFFFF0000u);
                *(uint32_t*)(jb.Cl + o0) = pkbf(s00, s01);
                *(uint32_t*)(jb.Cl + o1) = pkbf(s10, s11);
            }
        }
    }
}

// ---------------- classifier ----------------
__global__ void classifier_kernel(const __nv_bfloat16* __restrict__ hh,
                                  const __nv_bfloat16* __restrict__ hl,
                                  const float* __restrict__ Wout,
                                  const float* __restrict__ bout,
                                  float* __restrict__ out) {
    int warp = (blockIdx.x * blockDim.x + threadIdx.x) >> 5;
    int lane = threadIdx.x & 31;
    if (warp >= BATCH * OUTDIM) return;
    int b = warp / OUTDIM, o = warp % OUTDIM;
    const __nv_bfloat16* rh = hh + (size_t)b * HPAD;
    const __nv_bfloat16* rl = hl + (size_t)b * HPAD;
    const float* wr = Wout + (size_t)o * HID;
    float s = 0.0f;
    for (int k = lane; k < HID; k += 32)
        s += (__bfloat162float(rh[k]) + __bfloat162float(rl[k])) * wr[k];
    #pragma unroll
    for (int off = 16; off; off >>= 1) s += __shfl_down_sync(0xffffffff, s, off);
    if (lane == 0) out[b * OUTDIM + o] = s + bout[o];
}

// ---------------- host ----------------
extern "C" void kernel_launch(void* const* d_in, const int* in_sizes, int n_in,
                              void* d_out, int out_size) {
    const float* xs   = (const float*)d_in[0];
    const float* Wih0 = (const float*)d_in[1];
    const float* Whh0 = (const float*)d_in[2];
    const float* bih0 = (const float*)d_in[3];
    const float* bhh0 = (const float*)d_in[4];
    const float* Wih1 = (const float*)d_in[5];
    const float* Whh1 = (const float*)d_in[6];
    const float* bih1 = (const float*)d_in[7];
    const float* bhh1 = (const float*)d_in[8];
    const float* Wout = (const float*)d_in[9];
    const float* bout = (const float*)d_in[10];
    float* out = (float*)d_out;

    static int attr_done = 0;
    if (!attr_done) {
        cudaFuncSetAttribute(cell_kernel, cudaFuncAttributeMaxDynamicSharedMemorySize,
                             SMEM_BYTES);
        attr_done = 1;
    }

    void* p;
    __nv_bfloat16 *xh, *xl, *wh, *wl, *h0h, *h0l, *h1h, *h1l;
    cudaGetSymbolAddress(&p, gx_h);  xh  = (__nv_bfloat16*)p;
    cudaGetSymbolAddress(&p, gx_l);  xl  = (__nv_bfloat16*)p;
    cudaGetSymbolAddress(&p, gW_h);  wh  = (__nv_bfloat16*)p;
    cudaGetSymbolAddress(&p, gW_l);  wl  = (__nv_bfloat16*)p;
    cudaGetSymbolAddress(&p, gh0_h); h0h = (__nv_bfloat16*)p;
    cudaGetSymbolAddress(&p, gh0_l); h0l = (__nv_bfloat16*)p;
    cudaGetSymbolAddress(&p, gh1_h); h1h = (__nv_bfloat16*)p;
    cudaGetSymbolAddress(&p, gh1_l); h1l = (__nv_bfloat16*)p;

    {
        long tx = (long)TSTEPS * BATCH * XPAD;
        convert_pad_kernel<<<(unsigned)((tx + 255) / 256), 256>>>(
            xh, xl, xs, TSTEPS * BATCH, INDIM, XPAD, tx);
        long t0 = (long)NPAD * XPAD;
        convert_pad_kernel<<<(unsigned)((t0 + 255) / 256), 256>>>(
            wh + W_IH0_OFF, wl + W_IH0_OFF, Wih0, HID, INDIM, XPAD, t0);
        long th = (long)NPAD * HPAD;
        convert_pad_kernel<<<(unsigned)((th + 255) / 256), 256>>>(
            wh + W_HH0_OFF, wl + W_HH0_OFF, Whh0, HID, HID, HPAD, th);
        convert_pad_kernel<<<(unsigned)((th + 255) / 256), 256>>>(
            wh + W_IH1_OFF, wl + W_IH1_OFF, Wih1, HID, HID, HPAD, th);
        convert_pad_kernel<<<(unsigned)((th + 255) / 256), 256>>>(
            wh + W_HH1_OFF, wl + W_HH1_OFF, Whh1, HID, HID, HPAD, th);
        init_kernel<<<(2 * BATCH * HPAD + 255) / 256, 256>>>();
    }

    const size_t HP = (size_t)BATCH * HPAD;
    const size_t XT = (size_t)BATCH * XPAD;

    // t = 0: layer0 only
    {
        Job j0;
        j0.s[0] = { xh, xl, wh + W_IH0_OFF, wl + W_IH0_OFF, XPAD, XPAD / KC };
        j0.s[1] = { h0h + HP, h0l + HP, wh + W_HH0_OFF, wl + W_HH0_OFF, HPAD, HPAD / KC };
        j0.b1 = bih0; j0.b2 = bhh0;
        j0.Ch = h0h; j0.Cl = h0l;
        cell_kernel<<<GRID, TPB, SMEM_BYTES>>>(j0, j0, 0, TILES);
    }

    // t = 1..127: fused h0(t) || h1(t-1); heavy layer1 job first
    for (int t = 1; t < TSTEPS; t++) {
        const size_t pPrev = (size_t)((t - 1) & 1) * HP;
        const size_t pCur  = (size_t)(t & 1) * HP;
        Job j1;
        j1.s[0] = { h0h + pPrev, h0l + pPrev, wh + W_IH1_OFF, wl + W_IH1_OFF, HPAD, HPAD / KC };
        j1.s[1] = { h1h + pCur,  h1l + pCur,  wh + W_HH1_OFF, wl + W_HH1_OFF, HPAD, HPAD / KC };
        j1.b1 = bih1; j1.b2 = bhh1;
        j1.Ch = h1h + pPrev; j1.Cl = h1l + pPrev;
        Job j0;
        j0.s[0] = { xh + (size_t)t * XT, xl + (size_t)t * XT,
                    wh + W_IH0_OFF, wl + W_IH0_OFF, XPAD, XPAD / KC };
        j0.s[1] = { h0h + pPrev, h0l + pPrev, wh + W_HH0_OFF, wl + W_HH0_OFF, HPAD, HPAD / KC };
        j0.b1 = bih0; j0.b2 = bhh0;
        j0.Ch = h0h + pCur; j0.Cl = h0l + pCur;
        cell_kernel<<<GRID, TPB, SMEM_BYTES>>>(j1, j0, t, 2 * TILES);
    }

    // drain: h1(127)
    {
        Job jf;
        jf.s[0] = { h0h + HP, h0l + HP, wh + W_IH1_OFF, wl + W_IH1_OFF, HPAD, HPAD / KC };
        jf.s[1] = { h1h, h1l, wh + W_HH1_OFF, wl + W_HH1_OFF, HPAD, HPAD / KC };
        jf.b1 = bih1; jf.b2 = bhh1;
        jf.Ch = h1h + HP; jf.Cl = h1l + HP;
        cell_kernel<<<GRID, TPB, SMEM_BYTES>>>(jf, jf, TSTEPS, TILES);
    }

    classifier_kernel<<<(BATCH * OUTDIM * 32 + 255) / 256, 256>>>(
        h1h + HP, h1l + HP, Wout, bout, out);
}

// round 10
// speedup vs baseline: 1.1277x; 1.1277x over previous
#include <cuda_runtime.h>
#include <cuda_bf16.h>
#include <stdint.h>
#include <math.h>

// ---------------- problem constants ----------------
#define TSTEPS 128
#define BATCH  1024
#define INDIM  47
#define HID    646
#define OUTDIM 5

// ---------------- tiling ----------------
#define MTILE 128
#define NTILE 64
#define KC    32                  // k-chunk (bf16)
#define NT    11                  // n-tiles over NPAD
#define TILES 88                  // per job
#define NPAD  704                 // W out-dim pad (n tiling)
#define HPAD  672                 // h k-dim pad (21 * 32)
#define XPAD  64
#define TPB   256
#define GRID  148                 // 1 CTA / SM — tiles run sequentially per SM

#define SST    40                 // smem row stride (bf16)
#define A_TILE (MTILE * SST)      // 5120 bf16
#define W_TILE (NTILE * SST)      // 2560 bf16
#define STAGE  (2 * A_TILE + 2 * W_TILE)   // 15360 bf16
#define NSTAGE 3
#define SMEM_BYTES (NSTAGE * STAGE * 2)    // 92160 B

// ---------------- device globals (no allocation allowed) ----------------
#define W_IH0_OFF 0
#define W_HH0_OFF (NPAD * XPAD)
#define W_IH1_OFF (W_HH0_OFF + NPAD * HPAD)
#define W_HH1_OFF (W_IH1_OFF + NPAD * HPAD)
#define W_TOT     (W_HH1_OFF + NPAD * HPAD)

#define NX ((long)TSTEPS * BATCH * XPAD)   // 8388608
#define NH (2 * BATCH * HPAD)              // 1376256

__device__ __align__(16) __nv_bfloat16 gx_h[NX];
__device__ __align__(16) __nv_bfloat16 gx_l[NX];
__device__ __align__(16) __nv_bfloat16 gW_h[W_TOT];
__device__ __align__(16) __nv_bfloat16 gW_l[W_TOT];
__device__ __align__(16) __nv_bfloat16 gh0_h[NH];
__device__ __align__(16) __nv_bfloat16 gh0_l[NH];
__device__ __align__(16) __nv_bfloat16 gh1_h[NH];
__device__ __align__(16) __nv_bfloat16 gh1_l[NH];
__device__ unsigned int g_counter[TSTEPS + 2];

// ---------------- helpers ----------------
__device__ __forceinline__ uint32_t pkbf(float lo, float hi) {
    uint32_t r;
    asm("cvt.rn.bf16x2.f32 %0, %1, %2;" : "=r"(r) : "f"(hi), "f"(lo));
    return r;
}
__device__ __forceinline__ float fast_tanh(float x) {
    float e = __expf(2.0f * x);
    return 1.0f - __fdividef(2.0f, e + 1.0f);
}
__device__ __forceinline__ void mma_bf16(float* d, const uint32_t a[4], const uint32_t* b) {
    asm volatile(
        "mma.sync.aligned.m16n8k16.row.col.f32.bf16.bf16.f32 "
        "{%0,%1,%2,%3}, {%4,%5,%6,%7}, {%8,%9}, {%0,%1,%2,%3};"
        : "+f"(d[0]), "+f"(d[1]), "+f"(d[2]), "+f"(d[3])
        : "r"(a[0]), "r"(a[1]), "r"(a[2]), "r"(a[3]), "r"(b[0]), "r"(b[1]));
}
#define LDSM_X4(R, addr) \
    asm volatile("ldmatrix.sync.aligned.m8n8.x4.shared.b16 {%0,%1,%2,%3}, [%4];" \
        : "=r"((R)[0]), "=r"((R)[1]), "=r"((R)[2]), "=r"((R)[3]) : "r"(addr))
#define CPA16(dst, src) \
    asm volatile("cp.async.cg.shared.global [%0], [%1], 16;" :: "r"(dst), "l"(src))
#define CPA_COMMIT() asm volatile("cp.async.commit_group;" ::: "memory")
#define CPA_WAIT0()  asm volatile("cp.async.wait_group 0;" ::: "memory")
#define CPA_WAIT1()  asm volatile("cp.async.wait_group 1;" ::: "memory")

// ---------------- single fused preprocessing kernel ----------------
__device__ __forceinline__ void split_one(__nv_bfloat16* dh, __nv_bfloat16* dl,
                                          const float* src, long i,
                                          int rreal, int creal, int cpad) {
    int r = (int)(i / cpad), c = (int)(i % cpad);
    float v = (r < rreal && c < creal) ? src[(long)r * creal + c] : 0.0f;
    __nv_bfloat16 hi = __float2bfloat16(v);
    dh[i] = hi;
    dl[i] = __float2bfloat16(v - __bfloat162float(hi));
}

#define NW0 ((long)NPAD * XPAD)    // 45056
#define NWH ((long)NPAD * HPAD)    // 473088

__global__ void prep_kernel(const float* __restrict__ xs,
                            const float* __restrict__ Wih0,
                            const float* __restrict__ Whh0,
                            const float* __restrict__ Wih1,
                            const float* __restrict__ Whh1) {
    long i = (long)blockIdx.x * blockDim.x + threadIdx.x;
    if (i < NX) split_one(gx_h, gx_l, xs, i, TSTEPS * BATCH, INDIM, XPAD);
    if (i < NW0)
        split_one(gW_h + W_IH0_OFF, gW_l + W_IH0_OFF, Wih0, i, HID, INDIM, XPAD);
    if (i < NWH) {
        split_one(gW_h + W_HH0_OFF, gW_l + W_HH0_OFF, Whh0, i, HID, HID, HPAD);
        split_one(gW_h + W_IH1_OFF, gW_l + W_IH1_OFF, Wih1, i, HID, HID, HPAD);
        split_one(gW_h + W_HH1_OFF, gW_l + W_HH1_OFF, Whh1, i, HID, HID, HPAD);
    }
    if (i < NH) {
        __nv_bfloat16 z = __float2bfloat16(0.0f);
        gh0_h[i] = z; gh0_l[i] = z; gh1_h[i] = z; gh1_l[i] = z;
    }
    if (i < TSTEPS + 2) g_counter[i] = 0u;
}

// ---------------- cell kernel ----------------
struct Seg {
    const __nv_bfloat16 *Ah, *Al;
    const __nv_bfloat16 *Wh, *Wl;
    int kpad, chunks;
};
struct Job {
    Seg s[2];
    const float *b1, *b2;
    __nv_bfloat16 *Ch, *Cl;
};

__device__ __forceinline__ void issue_chunk(const Job& jb, int c, int m0, int n0,
                                            int tid, uint32_t st_u32) {
    const Seg& S = (c < jb.s[0].chunks) ? jb.s[0] : jb.s[1];
    const int cc = (c < jb.s[0].chunks) ? c : c - jb.s[0].chunks;
    const int col0 = cc * KC;
    const size_t kp = S.kpad;
    const int r0 = tid >> 2,          c8a = (tid & 3) * 8;
    const int r1 = (tid + 256) >> 2,  c8b = ((tid + 256) & 3) * 8;
    const __nv_bfloat16* ah = S.Ah + (size_t)m0 * kp + col0;
    const __nv_bfloat16* al = S.Al + (size_t)m0 * kp + col0;
    CPA16(st_u32 + (r0 * SST + c8a) * 2,                ah + (size_t)r0 * kp + c8a);
    CPA16(st_u32 + (r1 * SST + c8b) * 2,                ah + (size_t)r1 * kp + c8b);
    CPA16(st_u32 + (A_TILE + r0 * SST + c8a) * 2,       al + (size_t)r0 * kp + c8a);
    CPA16(st_u32 + (A_TILE + r1 * SST + c8b) * 2,       al + (size_t)r1 * kp + c8b);
    const int nr = tid >> 2, nc = (tid & 3) * 8;
    CPA16(st_u32 + (2 * A_TILE + nr * SST + nc) * 2,
          S.Wh + (size_t)(n0 + nr) * kp + col0 + nc);
    CPA16(st_u32 + (2 * A_TILE + W_TILE + nr * SST + nc) * 2,
          S.Wl + (size_t)(n0 + nr) * kp + col0 + nc);
}

__global__ __launch_bounds__(TPB, 1) void cell_kernel(Job jH, Job jL,
                                                      int cidx, int ntiles) {
    extern __shared__ __nv_bfloat16 sm[];
    __shared__ float s_bias[NTILE];
    __shared__ unsigned int s_idx;

    const int tid = threadIdx.x, lane = tid & 31, wid = tid >> 5;
    const int wm0 = (wid & 3) * 32;
    const int wn0 = (wid >> 2) * 32;
    const int r0 = lane >> 2;
    const int c0 = (lane & 3) * 2;

    const uint32_t sm_u32 = (uint32_t)__cvta_generic_to_shared(sm);

    const int lt = lane >> 3, lr = lane & 7;
    uint32_t offA[2][2];
    #pragma unroll
    for (int i = 0; i < 2; i++)
        #pragma unroll
        for (int s = 0; s < 2; s++)
            offA[i][s] = ((wm0 + i * 16 + (lt & 1) * 8 + lr) * SST + s * 16 + (lt >> 1) * 8) * 2;
    uint32_t offB[2][2];
    #pragma unroll
    for (int jp = 0; jp < 2; jp++)
        #pragma unroll
        for (int s = 0; s < 2; s++)
            offB[jp][s] = ((wn0 + (2 * jp + (lt >> 1)) * 8 + lr) * SST + s * 16 + (lt & 1) * 8) * 2;

    for (;;) {
        if (tid == 0) s_idx = atomicAdd(&g_counter[cidx], 1u);
        __syncthreads();   // s_idx handoff + all warps done with prev tile's smem/bias
        const unsigned int idx = s_idx;
        if (idx >= (unsigned int)ntiles) break;

        const Job& jb = (idx < TILES) ? jH : jL;
        const int tile = (idx < TILES) ? (int)idx : (int)idx - TILES;
        const int m0 = (tile / NT) * MTILE;
        const int n0 = (tile % NT) * NTILE;

        if (tid < NTILE) {
            int n = n0 + tid;
            s_bias[tid] = (n < HID) ? (jb.b1[n] + jb.b2[n]) : 0.0f;
        }

        float acc[2][4][4] = {};
        const int nch = jb.s[0].chunks + jb.s[1].chunks;   // >= 23

        issue_chunk(jb, 0, m0, n0, tid, sm_u32);
        CPA_COMMIT();
        issue_chunk(jb, 1, m0, n0, tid, sm_u32 + STAGE * 2);
        CPA_COMMIT();

        int bc = 0, bn = 2;
        for (int c = 0; c < nch; c++) {
            if (c + 1 < nch) CPA_WAIT1(); else CPA_WAIT0();
            __syncthreads();  // chunk c visible; buffer bn (= c-1's) reusable
            if (c + 2 < nch) {
                issue_chunk(jb, c + 2, m0, n0, tid, sm_u32 + bn * STAGE * 2);
                CPA_COMMIT();
            }

            const uint32_t sb = sm_u32 + bc * STAGE * 2;
            #pragma unroll
            for (int s = 0; s < 2; s++) {
                uint32_t ah[2][4], al[2][4], bh[2][4], bl[2][4];
                #pragma unroll
                for (int i = 0; i < 2; i++) {
                    LDSM_X4(ah[i], sb + offA[i][s]);
                    LDSM_X4(al[i], sb + offA[i][s] + A_TILE * 2);
                }
                #pragma unroll
                for (int jp = 0; jp < 2; jp++) {
                    LDSM_X4(bh[jp], sb + offB[jp][s] + 2 * A_TILE * 2);
                    LDSM_X4(bl[jp], sb + offB[jp][s] + (2 * A_TILE + W_TILE) * 2);
                }
                #pragma unroll
                for (int i = 0; i < 2; i++)
                    #pragma unroll
                    for (int j = 0; j < 4; j++) {
                        const uint32_t* pbh = &bh[j >> 1][(j & 1) * 2];
                        const uint32_t* pbl = &bl[j >> 1][(j & 1) * 2];
                        mma_bf16(acc[i][j], ah[i], pbh);
                        mma_bf16(acc[i][j], ah[i], pbl);
                        mma_bf16(acc[i][j], al[i], pbh);
                    }
            }
            bc = (bc == NSTAGE - 1) ? 0 : bc + 1;
            bn = (bn == NSTAGE - 1) ? 0 : bn + 1;
        }

        // epilogue: bias + tanh, store bf16 hi/lo pairs (cols >= HPAD skipped:
        // storage rows are HPAD wide; n-tiling covers up to NPAD)
        #pragma unroll
        for (int i = 0; i < 2; i++) {
            const int grow = m0 + wm0 + i * 16 + r0;
            #pragma unroll
            for (int j = 0; j < 4; j++) {
                const int col = wn0 + j * 8 + c0;
                if (n0 + col >= HPAD) continue;    // col even; pair in-bounds iff col < HPAD
                const float bv0 = s_bias[col], bv1 = s_bias[col + 1];
                const size_t o0 = (size_t)grow * HPAD + n0 + col;
                const size_t o1 = (size_t)(grow + 8) * HPAD + n0 + col;
                float t00 = fast_tanh(acc[i][j][0] + bv0);
                float t01 = fast_tanh(acc[i][j][1] + bv1);
                float t10 = fast_tanh(acc[i][j][2] + bv0);
                float t11 = fast_tanh(acc[i][j][3] + bv1);
                uint32_t u0 = pkbf(t00, t01);
                uint32_t u1 = pkbf(t10, t11);
                *(uint32_t*)(jb.Ch + o0) = u0;
                *(uint32_t*)(jb.Ch + o1) = u1;
                float s00 = t00 - __uint_as_float(u0 << 16);
                float s01 = t01 - __uint_as_float(u0 & 0xFFFF0000u);
                float s10 = t10 - __uint_as_float(u1 << 16);
                float s11 = t11 - __uint_as_float(u1 & 0xFFFF0000u);
                *(uint32_t*)(jb.Cl + o0) = pkbf(s00, s01);
                *(uint32_t*)(jb.Cl + o1) = pkbf(s10, s11);
            }
        }
    }
}

// ---------------- classifier ----------------
__global__ void classifier_kernel(const __nv_bfloat16* __restrict__ hh,
                                  const __nv_bfloat16* __restrict__ hl,
                                  const float* __restrict__ Wout,
                                  const float* __restrict__ bout,
                                  float* __restrict__ out) {
    int warp = (blockIdx.x * blockDim.x + threadIdx.x) >> 5;
    int lane = threadIdx.x & 31;
    if (warp >= BATCH * OUTDIM) return;
    int b = warp / OUTDIM, o = warp % OUTDIM;
    const __nv_bfloat16* rh = hh + (size_t)b * HPAD;
    const __nv_bfloat16* rl = hl + (size_t)b * HPAD;
    const float* wr = Wout + (size_t)o * HID;
    float s = 0.0f;
    for (int k = lane; k < HID; k += 32)
        s += (__bfloat162float(rh[k]) + __bfloat162float(rl[k])) * wr[k];
    #pragma unroll
    for (int off = 16; off; off >>= 1) s += __shfl_down_sync(0xffffffff, s, off);
    if (lane == 0) out[b * OUTDIM + o] = s + bout[o];
}

// ---------------- host ----------------
extern "C" void kernel_launch(void* const* d_in, const int* in_sizes, int n_in,
                              void* d_out, int out_size) {
    const float* xs   = (const float*)d_in[0];
    const float* Wih0 = (const float*)d_in[1];
    const float* Whh0 = (const float*)d_in[2];
    const float* bih0 = (const float*)d_in[3];
    const float* bhh0 = (const float*)d_in[4];
    const float* Wih1 = (const float*)d_in[5];
    const float* Whh1 = (const float*)d_in[6];
    const float* bih1 = (const float*)d_in[7];
    const float* bhh1 = (const float*)d_in[8];
    const float* Wout = (const float*)d_in[9];
    const float* bout = (const float*)d_in[10];
    float* out = (float*)d_out;

    static int attr_done = 0;
    if (!attr_done) {
        cudaFuncSetAttribute(cell_kernel, cudaFuncAttributeMaxDynamicSharedMemorySize,
                             SMEM_BYTES);
        attr_done = 1;
    }

    void* p;
    __nv_bfloat16 *xh, *xl, *wh, *wl, *h0h, *h0l, *h1h, *h1l;
    cudaGetSymbolAddress(&p, gx_h);  xh  = (__nv_bfloat16*)p;
    cudaGetSymbolAddress(&p, gx_l);  xl  = (__nv_bfloat16*)p;
    cudaGetSymbolAddress(&p, gW_h);  wh  = (__nv_bfloat16*)p;
    cudaGetSymbolAddress(&p, gW_l);  wl  = (__nv_bfloat16*)p;
    cudaGetSymbolAddress(&p, gh0_h); h0h = (__nv_bfloat16*)p;
    cudaGetSymbolAddress(&p, gh0_l); h0l = (__nv_bfloat16*)p;
    cudaGetSymbolAddress(&p, gh1_h); h1h = (__nv_bfloat16*)p;
    cudaGetSymbolAddress(&p, gh1_l); h1l = (__nv_bfloat16*)p;

    // ONE preprocessing launch (split/pad all operands, zero h + counters)
    prep_kernel<<<(unsigned)((NX + 255) / 256), 256>>>(xs, Wih0, Whh0, Wih1, Whh1);

    const size_t HP = (size_t)BATCH * HPAD;
    const size_t XT = (size_t)BATCH * XPAD;
    const int XCHN = XPAD / KC;   // 2
    const int HCHN = HPAD / KC;   // 21

    // t = 0: layer0 only
    {
        Job j0;
        j0.s[0] = { xh, xl, wh + W_IH0_OFF, wl + W_IH0_OFF, XPAD, XCHN };
        j0.s[1] = { h0h + HP, h0l + HP, wh + W_HH0_OFF, wl + W_HH0_OFF, HPAD, HCHN };
        j0.b1 = bih0; j0.b2 = bhh0;
        j0.Ch = h0h; j0.Cl = h0l;
        cell_kernel<<<GRID, TPB, SMEM_BYTES>>>(j0, j0, 0, TILES);
    }

    // t = 1..127: fused h0(t) || h1(t-1); heavy layer1 job first
    for (int t = 1; t < TSTEPS; t++) {
        const size_t pPrev = (size_t)((t - 1) & 1) * HP;
        const size_t pCur  = (size_t)(t & 1) * HP;
        Job j1;
        j1.s[0] = { h0h + pPrev, h0l + pPrev, wh + W_IH1_OFF, wl + W_IH1_OFF, HPAD, HCHN };
        j1.s[1] = { h1h + pCur,  h1l + pCur,  wh + W_HH1_OFF, wl + W_HH1_OFF, HPAD, HCHN };
        j1.b1 = bih1; j1.b2 = bhh1;
        j1.Ch = h1h + pPrev; j1.Cl = h1l + pPrev;
        Job j0;
        j0.s[0] = { xh + (size_t)t * XT, xl + (size_t)t * XT,
                    wh + W_IH0_OFF, wl + W_IH0_OFF, XPAD, XCHN };
        j0.s[1] = { h0h + pPrev, h0l + pPrev, wh + W_HH0_OFF, wl + W_HH0_OFF, HPAD, HCHN };
        j0.b1 = bih0; j0.b2 = bhh0;
        j0.Ch = h0h + pCur; j0.Cl = h0l + pCur;
        cell_kernel<<<GRID, TPB, SMEM_BYTES>>>(j1, j0, t, 2 * TILES);
    }

    // drain: h1(127)
    {
        Job jf;
        jf.s[0] = { h0h + HP, h0l + HP, wh + W_IH1_OFF, wl + W_IH1_OFF, HPAD, HCHN };
        jf.s[1] = { h1h, h1l, wh + W_HH1_OFF, wl + W_HH1_OFF, HPAD, HCHN };
        jf.b1 = bih1; jf.b2 = bhh1;
        jf.Ch = h1h + HP; jf.Cl = h1l + HP;
        cell_kernel<<<GRID, TPB, SMEM_BYTES>>>(jf, jf, TSTEPS, TILES);
    }

    classifier_kernel<<<(BATCH * OUTDIM * 32 + 255) / 256, 256>>>(
        h1h + HP, h1l + HP, Wout, bout, out);
}